// round 11
// baseline (speedup 1.0000x reference)
#include <cuda_runtime.h>
#include <math.h>

// Problem shapes (fixed by dataset)
#define SS 2048
#define BB 32
#define HH 1024

// u GEMM tiling: 128 o-chunks of 8, 4 h-chunks of 256 -> 512 blocks
#define NOB 128
#define OC  8

#define GRID 148   // persistent co-resident blocks for scores+softmax

// Scratch (static __device__ — no allocations allowed)
__device__ float g_u_part[NOB][BB * HH];  // 16 MB (L2-resident)
__device__ float g_u[BB * HH];            // 128 KB
__device__ float g_scores[BB * SS];       // 256 KB
__device__ unsigned g_bar;                // single grid-barrier counter

// ---------------------------------------------------------------------------
// K_A: u_part[j][b][h] = sum_{o in chunk j} hidden[b,o] * W[o,h]
// grid (HH/256, NOB) = (4, 128) = 512 blocks, 256 threads.
// KEY CHANGE vs R9: hidden smem tile is read as float4 over b, so one
// LDS.128 broadcast feeds 4 FMAs (was 1 scalar LDS per FMA -> the kernel
// was LDS-port bound at ~7K LDS-instr/SM). W loads batched (MLP=8).
// ---------------------------------------------------------------------------
__global__ void k_upart(const float* __restrict__ hidden,
                        const float* __restrict__ W) {
    __shared__ float hs[OC * BB];  // hs[o*BB + b] = hidden[b, o0+o]
    const int t = threadIdx.x;
    const int h = blockIdx.x * 256 + t;
    const int o0 = blockIdx.y * OC;

    if (t < OC * BB) {             // 256 threads load 256 hidden values
        int o = t >> 5, b = t & 31;
        hs[t] = hidden[b * HH + o0 + o];
    }
    __syncthreads();

    // Batch the 8 W loads up front (independent, MLP=8)
    float w[OC];
#pragma unroll
    for (int o = 0; o < OC; ++o)
        w[o] = W[(size_t)(o0 + o) * HH + h];

    float acc[BB];
#pragma unroll
    for (int b = 0; b < BB; ++b) acc[b] = 0.f;

    const float4* hs4 = reinterpret_cast<const float4*>(hs);  // [o][bq] bq<8
#pragma unroll
    for (int o = 0; o < OC; ++o) {
#pragma unroll
        for (int bq = 0; bq < BB / 4; ++bq) {
            float4 hv = hs4[o * (BB / 4) + bq];   // warp-broadcast LDS.128
            acc[bq * 4 + 0] = fmaf(hv.x, w[o], acc[bq * 4 + 0]);
            acc[bq * 4 + 1] = fmaf(hv.y, w[o], acc[bq * 4 + 1]);
            acc[bq * 4 + 2] = fmaf(hv.z, w[o], acc[bq * 4 + 2]);
            acc[bq * 4 + 3] = fmaf(hv.w, w[o], acc[bq * 4 + 3]);
        }
    }

#pragma unroll
    for (int b = 0; b < BB; ++b) g_u_part[blockIdx.y][b * HH + h] = acc[b];
}

// ---------------------------------------------------------------------------
// K_B: u[i] = sum over 128 partials (16 MB, L2-hot). Two-level:
// grid 256 x 256 thr; thread t: output j = t&127, partial half g = t>>7
// (64 partials each, unrolled), pair-combine via smem.
// ---------------------------------------------------------------------------
__global__ void __launch_bounds__(256) k_ureduce() {
    __shared__ float tmp[256];
    const int t = threadIdx.x;
    const int j = blockIdx.x * 128 + (t & 127);   // output index < 32768
    const int g = t >> 7;                         // 0 or 1

    float s = 0.f;
#pragma unroll 8
    for (int p = g * 64; p < g * 64 + 64; ++p) s += g_u_part[p][j];
    tmp[t] = s;
    __syncthreads();
    if (t < 128) g_u[j] = tmp[t] + tmp[t + 128];
}

// ---------------------------------------------------------------------------
// K_C: persistent scores (static, sync-free) + ONE grid barrier + softmax.
// Scores: warp w <-> batch b = w; u[b] pinned in 8 float4 regs. Tasks are
// single s, interleaved s = blk + k*GRID. Each task = one contiguous 128 KB
// slab enc[s,:,:], one 4 KB row per warp (8x LDG.128, __ldcs evict-first).
// Softmax: after the barrier, blocks 0..31 normalize row b = blockIdx.x.
// ---------------------------------------------------------------------------
__global__ void __launch_bounds__(1024, 1)
k_scores_softmax(const float* __restrict__ enc, float* __restrict__ out) {
    const int t = threadIdx.x;
    const int warp = t >> 5;
    const int lane = t & 31;
    const int b = warp;
    const int blk = blockIdx.x;

    __shared__ float red[32];

    const float4* ub = reinterpret_cast<const float4*>(g_u + b * HH);
    float4 u[8];
#pragma unroll
    for (int c = 0; c < 8; ++c) u[c] = ub[c * 32 + lane];

    // ---- Phase 1: scores, static interleaved tasks, no syncs ----
    for (int s = blk; s < SS; s += GRID) {
        const float4* r =
            reinterpret_cast<const float4*>(enc + ((size_t)s * BB + b) * HH);
        float a = 0.f;
#pragma unroll
        for (int c = 0; c < 8; ++c) {
            float4 e = __ldcs(&r[c * 32 + lane]);
            a += e.x * u[c].x + e.y * u[c].y + e.z * u[c].z + e.w * u[c].w;
        }
#pragma unroll
        for (int off = 16; off; off >>= 1)
            a += __shfl_xor_sync(0xFFFFFFFFu, a, off);
        if (lane == 0) g_scores[b * SS + s] = a;
    }

    // ---- ONE grid barrier among 148 equal-work blocks ----
    __syncthreads();
    if (t == 0) {
        __threadfence();                       // release scores
        atomicAdd(&g_bar, 1u);
        while (atomicAdd(&g_bar, 0u) < GRID) __nanosleep(32);
        __threadfence();                       // acquire
    }
    __syncthreads();

    // ---- Phase 2: softmax (blocks 0..31, batch bb = blk) ----
    if (blk < BB) {
        const int bb = blk;
        float v0 = g_scores[bb * SS + t];
        float v1 = g_scores[bb * SS + t + 1024];

        float m = fmaxf(v0, v1);
#pragma unroll
        for (int off = 16; off; off >>= 1)
            m = fmaxf(m, __shfl_xor_sync(0xFFFFFFFFu, m, off));
        if (lane == 0) red[warp] = m;
        __syncthreads();
        if (warp == 0) {
            float x = red[lane];
#pragma unroll
            for (int off = 16; off; off >>= 1)
                x = fmaxf(x, __shfl_xor_sync(0xFFFFFFFFu, x, off));
            if (lane == 0) red[0] = x;
        }
        __syncthreads();
        const float bm = red[0];
        __syncthreads();  // before reusing red[]

        v0 = __expf(v0 - bm);
        v1 = __expf(v1 - bm);
        float s = v0 + v1;
#pragma unroll
        for (int off = 16; off; off >>= 1)
            s += __shfl_xor_sync(0xFFFFFFFFu, s, off);
        if (lane == 0) red[warp] = s;
        __syncthreads();
        if (warp == 0) {
            float x = red[lane];
#pragma unroll
            for (int off = 16; off; off >>= 1)
                x += __shfl_xor_sync(0xFFFFFFFFu, x, off);
            if (lane == 0) red[0] = x;
        }
        __syncthreads();
        const float inv = 1.f / red[0];

        out[bb * SS + t]        = v0 * inv;
        out[bb * SS + t + 1024] = v1 * inv;
    }
}

// ---------------------------------------------------------------------------
// Inputs (metadata order): hidden [B,H], encoder_outputs [S,B,H], W [H,H], b [H]
// The bias input is mathematically irrelevant (softmax shift invariance).
// ---------------------------------------------------------------------------
extern "C" void kernel_launch(void* const* d_in, const int* in_sizes, int n_in,
                              void* d_out, int out_size) {
    const float* hidden = (const float*)d_in[0];
    const float* enc    = (const float*)d_in[1];
    const float* W      = (const float*)d_in[2];
    float* out          = (float*)d_out;

    // Zero the barrier counter each invocation (captured as a graph node).
    void* bar_ptr;
    cudaGetSymbolAddress(&bar_ptr, g_bar);
    cudaMemsetAsync(bar_ptr, 0, sizeof(unsigned));

    k_upart<<<dim3(HH / 256, NOB), 256>>>(hidden, W);
    k_ureduce<<<256, 256>>>();
    k_scores_softmax<<<GRID, 1024>>>(enc, out);
}

// round 12
// speedup vs baseline: 1.0370x; 1.0370x over previous
#include <cuda_runtime.h>
#include <math.h>

// Problem shapes (fixed by dataset)
#define SS 2048
#define BB 32
#define HH 1024

// u GEMM tiling: 64 o-chunks of 16, 4 h-chunks of 256, 2 b-halves -> 512 blocks
#define NOB 64
#define OC  16

#define GRID 148   // persistent co-resident blocks for scores+softmax

// Scratch (static __device__ — no allocations allowed)
__device__ float g_u_part[NOB][BB * HH];  // 8 MB (L2-resident)
__device__ float g_u[BB * HH];            // 128 KB
__device__ float g_scores[BB * SS];       // 256 KB
__device__ unsigned g_bar;                // single grid-barrier counter

// ---------------------------------------------------------------------------
// K_A: u_part[j][b][h] = sum_{o in chunk j} hidden[b,o] * W[o,h]
// grid (HH/256, NOB, 2) = 512 blocks, 256 threads. KEY CHANGE vs R10: each
// block covers a 16-b HALF -> acc[16] (~46 regs vs 72) -> 5-6 blocks/SM,
// occ ~2x (R10 ran latency-exposed at occ 31%, no pipe >35%). W is read
// twice (once per half); second pass hits L2 (4 MB). Partials 8 MB, L2-hot.
// ---------------------------------------------------------------------------
__global__ void k_upart(const float* __restrict__ hidden,
                        const float* __restrict__ W) {
    __shared__ float hs[OC * 16];  // hs[o*16 + bl] = hidden[bbase+bl, o0+o]
    const int t = threadIdx.x;
    const int h = blockIdx.x * 256 + t;
    const int o0 = blockIdx.y * OC;
    const int bbase = blockIdx.z * 16;

    if (t < OC * 16) {             // 256 threads load 256 hidden values
        int o = t >> 4, bl = t & 15;
        hs[t] = hidden[(bbase + bl) * HH + o0 + o];
    }
    __syncthreads();

    // Batch the 16 W loads up front (independent, MLP=16)
    float w[OC];
#pragma unroll
    for (int o = 0; o < OC; ++o)
        w[o] = W[(size_t)(o0 + o) * HH + h];

    float acc[16];
#pragma unroll
    for (int bl = 0; bl < 16; ++bl) acc[bl] = 0.f;

    const float4* hs4 = reinterpret_cast<const float4*>(hs);  // [o][q], q<4
#pragma unroll
    for (int o = 0; o < OC; ++o) {
#pragma unroll
        for (int q = 0; q < 4; ++q) {
            float4 hv = hs4[o * 4 + q];    // warp-broadcast LDS.128
            acc[q * 4 + 0] = fmaf(hv.x, w[o], acc[q * 4 + 0]);
            acc[q * 4 + 1] = fmaf(hv.y, w[o], acc[q * 4 + 1]);
            acc[q * 4 + 2] = fmaf(hv.z, w[o], acc[q * 4 + 2]);
            acc[q * 4 + 3] = fmaf(hv.w, w[o], acc[q * 4 + 3]);
        }
    }

#pragma unroll
    for (int bl = 0; bl < 16; ++bl)
        g_u_part[blockIdx.y][(bbase + bl) * HH + h] = acc[bl];
}

// ---------------------------------------------------------------------------
// K_B: u[i] = sum over 64 partials (8 MB, L2-hot). Two-level:
// grid 256 x 256 thr; thread t: output j = t&127, partial half g = t>>7
// (32 partials each, unrolled), pair-combine via smem.
// ---------------------------------------------------------------------------
__global__ void __launch_bounds__(256) k_ureduce() {
    __shared__ float tmp[256];
    const int t = threadIdx.x;
    const int j = blockIdx.x * 128 + (t & 127);   // output index < 32768
    const int g = t >> 7;                         // 0 or 1

    float s = 0.f;
#pragma unroll 8
    for (int p = g * 32; p < g * 32 + 32; ++p) s += g_u_part[p][j];
    tmp[t] = s;
    __syncthreads();
    if (t < 128) g_u[j] = tmp[t] + tmp[t + 128];
}

// ---------------------------------------------------------------------------
// K_C: persistent scores (static, sync-free) + ONE grid barrier + softmax.
// Scores: warp w <-> batch b = w; u[b] pinned in 8 float4 regs. Tasks are
// single s, interleaved s = blk + k*GRID. Each task = one contiguous 128 KB
// slab enc[s,:,:], one 4 KB row per warp (8x LDG.128, __ldcs evict-first).
// Softmax: after the barrier, blocks 0..31 normalize row b = blockIdx.x.
// ---------------------------------------------------------------------------
__global__ void __launch_bounds__(1024, 1)
k_scores_softmax(const float* __restrict__ enc, float* __restrict__ out) {
    const int t = threadIdx.x;
    const int warp = t >> 5;
    const int lane = t & 31;
    const int b = warp;
    const int blk = blockIdx.x;

    __shared__ float red[32];

    const float4* ub = reinterpret_cast<const float4*>(g_u + b * HH);
    float4 u[8];
#pragma unroll
    for (int c = 0; c < 8; ++c) u[c] = ub[c * 32 + lane];

    // ---- Phase 1: scores, static interleaved tasks, no syncs ----
    for (int s = blk; s < SS; s += GRID) {
        const float4* r =
            reinterpret_cast<const float4*>(enc + ((size_t)s * BB + b) * HH);
        float a = 0.f;
#pragma unroll
        for (int c = 0; c < 8; ++c) {
            float4 e = __ldcs(&r[c * 32 + lane]);
            a += e.x * u[c].x + e.y * u[c].y + e.z * u[c].z + e.w * u[c].w;
        }
#pragma unroll
        for (int off = 16; off; off >>= 1)
            a += __shfl_xor_sync(0xFFFFFFFFu, a, off);
        if (lane == 0) g_scores[b * SS + s] = a;
    }

    // ---- ONE grid barrier among 148 equal-work blocks ----
    __syncthreads();
    if (t == 0) {
        __threadfence();                       // release scores
        atomicAdd(&g_bar, 1u);
        while (atomicAdd(&g_bar, 0u) < GRID) __nanosleep(32);
        __threadfence();                       // acquire
    }
    __syncthreads();

    // ---- Phase 2: softmax (blocks 0..31, batch bb = blk) ----
    if (blk < BB) {
        const int bb = blk;
        float v0 = g_scores[bb * SS + t];
        float v1 = g_scores[bb * SS + t + 1024];

        float m = fmaxf(v0, v1);
#pragma unroll
        for (int off = 16; off; off >>= 1)
            m = fmaxf(m, __shfl_xor_sync(0xFFFFFFFFu, m, off));
        if (lane == 0) red[warp] = m;
        __syncthreads();
        if (warp == 0) {
            float x = red[lane];
#pragma unroll
            for (int off = 16; off; off >>= 1)
                x = fmaxf(x, __shfl_xor_sync(0xFFFFFFFFu, x, off));
            if (lane == 0) red[0] = x;
        }
        __syncthreads();
        const float bm = red[0];
        __syncthreads();  // before reusing red[]

        v0 = __expf(v0 - bm);
        v1 = __expf(v1 - bm);
        float s = v0 + v1;
#pragma unroll
        for (int off = 16; off; off >>= 1)
            s += __shfl_xor_sync(0xFFFFFFFFu, s, off);
        if (lane == 0) red[warp] = s;
        __syncthreads();
        if (warp == 0) {
            float x = red[lane];
#pragma unroll
            for (int off = 16; off; off >>= 1)
                x += __shfl_xor_sync(0xFFFFFFFFu, x, off);
            if (lane == 0) red[0] = x;
        }
        __syncthreads();
        const float inv = 1.f / red[0];

        out[bb * SS + t]        = v0 * inv;
        out[bb * SS + t + 1024] = v1 * inv;
    }
}

// ---------------------------------------------------------------------------
// Inputs (metadata order): hidden [B,H], encoder_outputs [S,B,H], W [H,H], b [H]
// The bias input is mathematically irrelevant (softmax shift invariance).
// ---------------------------------------------------------------------------
extern "C" void kernel_launch(void* const* d_in, const int* in_sizes, int n_in,
                              void* d_out, int out_size) {
    const float* hidden = (const float*)d_in[0];
    const float* enc    = (const float*)d_in[1];
    const float* W      = (const float*)d_in[2];
    float* out          = (float*)d_out;

    // Zero the barrier counter each invocation (captured as a graph node).
    void* bar_ptr;
    cudaGetSymbolAddress(&bar_ptr, g_bar);
    cudaMemsetAsync(bar_ptr, 0, sizeof(unsigned));

    k_upart<<<dim3(HH / 256, NOB, 2), 256>>>(hidden, W);
    k_ureduce<<<256, 256>>>();
    k_scores_softmax<<<GRID, 1024>>>(enc, out);
}